// round 9
// baseline (speedup 1.0000x reference)
#include <cuda_runtime.h>
#include <cuda_fp16.h>
#include <math.h>

// ---------------------------------------------------------------------------
// GIN (3 GINConv layers + BN + ReLU + MLP head)
//   N_NODES=100000, N_EDGES=1200000, D_IN=128, D_H=64, N_GRAPHS=256
// R8 changes vs R6 (R7 staging regressed and is reverted):
//   * pull fused INTO the layer kernels: each block gathers its 128 node
//     rows (self + CSR neighbors, fp16 -> fp32) straight into the k-major
//     smem tile, then runs the GEMMs. z buffer deleted; 3 launches deleted.
//   * hh double-buffered (gather reads vs row writes race otherwise).
//   * gemmA / CSR / epilogue identical to the 460us R6 build.
// ---------------------------------------------------------------------------

#define MAX_NODES 100000
#define MAX_EDGES 1200000
#define NGRAPH    256
#define SCAN_B    1024
#define MAX_SCAN_BLOCKS 128
#define TS 130                     // even padded node-stride (aligned LDS.64)

__device__ uint2 g_hhA [MAX_NODES * 16];    // fp16 activation rows (128B/node)
__device__ uint2 g_hhB [MAX_NODES * 16];
__device__ float g_pool[NGRAPH * 192];
__device__ int   g_deg [MAX_NODES + 1];
__device__ int   g_row [MAX_NODES + 1];
__device__ int   g_cur [MAX_NODES];
__device__ int   g_col [MAX_EDGES];
__device__ int   g_bsum[MAX_SCAN_BLOCKS];

typedef unsigned long long ull;

__device__ __forceinline__ ull pack2(float lo, float hi) {
    ull r; asm("mov.b64 %0,{%1,%2};" : "=l"(r) : "f"(lo), "f"(hi)); return r;
}
__device__ __forceinline__ void unpack2(ull v, float& lo, float& hi) {
    asm("mov.b64 {%0,%1},%2;" : "=f"(lo), "=f"(hi) : "l"(v));
}
__device__ __forceinline__ ull fma2(ull a, ull b, ull c) {
    ull d; asm("fma.rn.f32x2 %0,%1,%2,%3;" : "=l"(d) : "l"(a), "l"(b), "l"(c)); return d;
}
__device__ __forceinline__ float4 h2f4(uint2 u) {
    __half2 a = *(__half2*)&u.x, b = *(__half2*)&u.y;
    float2 fa = __half22float2(a), fb = __half22float2(b);
    return make_float4(fa.x, fa.y, fb.x, fb.y);
}
__device__ __forceinline__ uint2 f4h(float a, float b, float c, float d) {
    __half2 lo = __floats2half2_rn(a, b), hi = __floats2half2_rn(c, d);
    uint2 u; u.x = *(unsigned*)&lo; u.y = *(unsigned*)&hi; return u;
}

// One k-step: one weight row segment (32 cols) feeds TWO nodes' accumulators.
__device__ __forceinline__ void fma_k32_dual(ull* accA, ull* accB,
                                             const float* ws, int k, int halfoff,
                                             float va, float vb) {
    ull a2 = pack2(va, va), b2 = pack2(vb, vb);
    const ulonglong2* wrow = (const ulonglong2*)(ws + k * 64 + halfoff);
#pragma unroll
    for (int j8 = 0; j8 < 8; j8++) {
        ulonglong2 wv = wrow[j8];
        accA[j8 * 2 + 0] = fma2(a2, wv.x, accA[j8 * 2 + 0]);
        accA[j8 * 2 + 1] = fma2(a2, wv.y, accA[j8 * 2 + 1]);
        accB[j8 * 2 + 0] = fma2(b2, wv.x, accB[j8 * 2 + 0]);
        accB[j8 * 2 + 1] = fma2(b2, wv.y, accB[j8 * 2 + 1]);
    }
}

// BN(eval)+ReLU for col pair (j, j+1) applied to both nodes' packed values.
__device__ __forceinline__ void bn_pair(ull& va, ull& vb, int j,
    const float* __restrict__ b1, const float* __restrict__ gg,
    const float* __restrict__ bt, const float* __restrict__ rm,
    const float* __restrict__ rv)
{
    float sc0 = __ldg(gg + j)     * rsqrtf(__ldg(rv + j)     + 1e-5f);
    float sc1 = __ldg(gg + j + 1) * rsqrtf(__ldg(rv + j + 1) + 1e-5f);
    float sh0 = (__ldg(b1 + j)     - __ldg(rm + j))     * sc0 + __ldg(bt + j);
    float sh1 = (__ldg(b1 + j + 1) - __ldg(rm + j + 1)) * sc1 + __ldg(bt + j + 1);
    float a, b;
    unpack2(va, a, b);
    a = fmaxf(fmaf(a, sc0, sh0), 0.f);
    b = fmaxf(fmaf(b, sc1, sh1), 0.f);
    va = pack2(a, b);
    unpack2(vb, a, b);
    a = fmaxf(fmaf(a, sc0, sh0), 0.f);
    b = fmaxf(fmaf(b, sc1, sh1), 0.f);
    vb = pack2(a, b);
}

// Epilogue for one node's 32 cols: bias + ReLU + fp16 store + pool reduction.
__device__ __forceinline__ void epi_node(const ull* out16, int halfoff,
                                         const float* __restrict__ b2,
                                         uint2* hrow, float* prow, bool act)
{
    if (!act) return;
    int ubase = halfoff >> 2;
#pragma unroll
    for (int qq = 0; qq < 8; qq++) {
        int j = halfoff + qq * 4;
        float a0, a1, a2, a3;
        unpack2(out16[qq * 2 + 0], a0, a1);
        unpack2(out16[qq * 2 + 1], a2, a3);
        a0 = fmaxf(a0 + __ldg(b2 + j + 0), 0.f);
        a1 = fmaxf(a1 + __ldg(b2 + j + 1), 0.f);
        a2 = fmaxf(a2 + __ldg(b2 + j + 2), 0.f);
        a3 = fmaxf(a3 + __ldg(b2 + j + 3), 0.f);
        hrow[ubase + qq] = f4h(a0, a1, a2, a3);
        asm volatile("red.global.add.v4.f32 [%0], {%1,%2,%3,%4};"
                     :: "l"(prow + j), "f"(a0), "f"(a1), "f"(a2), "f"(a3)
                     : "memory");
    }
}

// Gather one node's aggregated fp32 row chunk (4 k-values per lane).
// lane in [0,16); returns sum over self + neighbors.
__device__ __forceinline__ float4 gather_node(const uint2* __restrict__ hh,
                                              const int* __restrict__ rowptr,
                                              const int* __restrict__ col,
                                              int node, int lane)
{
    float4 acc = h2f4(__ldg(hh + (size_t)node * 16 + lane));
    int e   = __ldg(rowptr + node);
    int end = __ldg(rowptr + node + 1);
    for (; e + 4 <= end; e += 4) {
        int s0 = __ldg(col + e),     s1 = __ldg(col + e + 1);
        int s2 = __ldg(col + e + 2), s3 = __ldg(col + e + 3);
        float4 v0 = h2f4(__ldg(hh + (size_t)s0 * 16 + lane));
        float4 v1 = h2f4(__ldg(hh + (size_t)s1 * 16 + lane));
        float4 v2 = h2f4(__ldg(hh + (size_t)s2 * 16 + lane));
        float4 v3 = h2f4(__ldg(hh + (size_t)s3 * 16 + lane));
        acc.x += (v0.x + v1.x) + (v2.x + v3.x);
        acc.y += (v0.y + v1.y) + (v2.y + v3.y);
        acc.z += (v0.z + v1.z) + (v2.z + v3.z);
        acc.w += (v0.w + v1.w) + (v2.w + v3.w);
    }
    for (; e < end; e++) {
        int s = __ldg(col + e);
        float4 v = h2f4(__ldg(hh + (size_t)s * 16 + lane));
        acc.x += v.x; acc.y += v.y; acc.z += v.z; acc.w += v.w;
    }
    return acc;
}

// ---------------------------------------------------------------------------
__global__ void zero_f_kernel(float* __restrict__ p, int n) {
    int i = blockIdx.x * blockDim.x + threadIdx.x;
    if (i < n) p[i] = 0.f;
}
__global__ void zero_i_kernel(int* __restrict__ p, int n) {
    int i = blockIdx.x * blockDim.x + threadIdx.x;
    if (i < n) p[i] = 0;
}

// ---------------------------------------------------------------------------
// CSR build
// ---------------------------------------------------------------------------
__global__ void hist_kernel(const int* __restrict__ ei, int* __restrict__ deg, int n_edges) {
    int e = blockIdx.x * blockDim.x + threadIdx.x;
    if (e < n_edges) atomicAdd(deg + __ldg(ei + n_edges + e), 1);
}

__global__ void bsum_kernel(const int* __restrict__ deg, int* __restrict__ bsum, int n) {
    __shared__ int sm[SCAN_B];
    int i = blockIdx.x * SCAN_B + threadIdx.x;
    sm[threadIdx.x] = (i < n) ? deg[i] : 0;
    __syncthreads();
#pragma unroll
    for (int off = SCAN_B / 2; off > 0; off >>= 1) {
        if (threadIdx.x < off) sm[threadIdx.x] += sm[threadIdx.x + off];
        __syncthreads();
    }
    if (threadIdx.x == 0) bsum[blockIdx.x] = sm[0];
}

__global__ void bscan_kernel(int* __restrict__ bsum, int nb) {
    if (threadIdx.x == 0) {
        int run = 0;
        for (int i = 0; i < nb; i++) { int v = bsum[i]; bsum[i] = run; run += v; }
    }
}

__global__ void scatter_scan_kernel(const int* __restrict__ deg,
                                    const int* __restrict__ bsum,
                                    int* __restrict__ rowptr, int* __restrict__ cur, int n) {
    __shared__ int sm[SCAN_B];
    int i = blockIdx.x * SCAN_B + threadIdx.x;
    int v = (i < n) ? deg[i] : 0;
    sm[threadIdx.x] = v;
    __syncthreads();
#pragma unroll
    for (int off = 1; off < SCAN_B; off *= 2) {
        int t = (threadIdx.x >= off) ? sm[threadIdx.x - off] : 0;
        __syncthreads();
        sm[threadIdx.x] += t;
        __syncthreads();
    }
    int excl = sm[threadIdx.x] - v + bsum[blockIdx.x];
    if (i < n) { rowptr[i] = excl; cur[i] = excl; }
    if (i == n - 1) rowptr[n] = excl + v;
}

__global__ void fill_kernel(const int* __restrict__ ei, int* __restrict__ cur,
                            int* __restrict__ col, int n_edges) {
    int e = blockIdx.x * blockDim.x + threadIdx.x;
    if (e >= n_edges) return;
    int s = __ldg(ei + e);
    int d = __ldg(ei + n_edges + e);
    int pos = atomicAdd(cur + d, 1);
    col[pos] = s;
}

// ---------------------------------------------------------------------------
// gemmA: hhA = fp16(x @ w1)  (x: [N,128]). 2 nodes/thread, 32 cols each.
// (unchanged from the 460us R6 build)
// ---------------------------------------------------------------------------
__global__ __launch_bounds__(128) void gemmA_kernel(
    const float* __restrict__ x, const float* __restrict__ w1,
    uint2* __restrict__ hh, int n_nodes)
{
    __shared__ float ws[128 * 64];   // 32KB
    int tid = threadIdx.x;
    for (int i = tid; i < 128 * 64; i += 128) ws[i] = w1[i];
    __syncthreads();

    int half = tid & 1, q = tid >> 1;
    int halfoff = half * 32;
    int n0 = blockIdx.x * 128 + 2 * q, n1 = n0 + 1;
    bool a0 = n0 < n_nodes, a1 = n1 < n_nodes;
    int n0c = a0 ? n0 : n_nodes - 1, n1c = a1 ? n1 : n_nodes - 1;

    ull acc[2][16];
#pragma unroll
    for (int j = 0; j < 16; j++) { acc[0][j] = 0ull; acc[1][j] = 0ull; }

    const float4* r0 = (const float4*)(x + (size_t)n0c * 128);
    const float4* r1 = (const float4*)(x + (size_t)n1c * 128);
#pragma unroll 4
    for (int k4 = 0; k4 < 32; k4++) {
        float4 v0 = __ldg(r0 + k4), v1 = __ldg(r1 + k4);
        float f0[4] = {v0.x, v0.y, v0.z, v0.w};
        float f1[4] = {v1.x, v1.y, v1.z, v1.w};
#pragma unroll
        for (int kk = 0; kk < 4; kk++)
            fma_k32_dual(acc[0], acc[1], ws, k4 * 4 + kk, halfoff, f0[kk], f1[kk]);
    }

    int ubase = halfoff >> 2;
#pragma unroll
    for (int nd = 0; nd < 2; nd++) {
        bool act = nd ? a1 : a0;
        if (!act) continue;
        int n = nd ? n1 : n0;
        uint2* orow = hh + (size_t)n * 16;
#pragma unroll
        for (int qq = 0; qq < 8; qq++) {
            float a, b, c, d;
            unpack2(acc[nd][qq * 2 + 0], a, b);
            unpack2(acc[nd][qq * 2 + 1], c, d);
            orow[ubase + qq] = f4h(a, b, c, d);
        }
    }
}

// ---------------------------------------------------------------------------
// fusedB (layer-1 tail): gather z=pull(hh_in); BN+ReLU at tile write;
// h = relu( hbn @ w2 + b2 ); fp16 store to hh_out + pool reduction.
// dyn smem: tile 64*TS + ws 64*64.
// ---------------------------------------------------------------------------
__global__ __launch_bounds__(128) void fusedB_kernel(
    const uint2* __restrict__ hh_in,
    const int* __restrict__ rowptr, const int* __restrict__ col,
    const float* __restrict__ b1,
    const float* __restrict__ gg, const float* __restrict__ bt,
    const float* __restrict__ rm, const float* __restrict__ rv,
    const float* __restrict__ w2, const float* __restrict__ b2,
    uint2*       __restrict__ hh_out,
    const int*   __restrict__ batch,
    float*       __restrict__ pool, int pool_off, int n_nodes)
{
    extern __shared__ float dsm[];
    float* tile = dsm;                 // [64][TS]
    float* ws   = dsm + 64 * TS;       // [64][64]
    __shared__ float2 scsh[64];
    int tid = threadIdx.x;

    if (tid < 64) {
        float sc = __ldg(gg + tid) * rsqrtf(__ldg(rv + tid) + 1e-5f);
        float sh = (__ldg(b1 + tid) - __ldg(rm + tid)) * sc + __ldg(bt + tid);
        scsh[tid] = make_float2(sc, sh);
    }
    for (int i = tid; i < 64 * 64; i += 128) ws[i] = w2[i];
    __syncthreads();

    int nbase = blockIdx.x * 128;
    // ---- gather phase: 16 threads/node, 8 nodes in flight ----
    {
        int gl = tid & 15, gn = tid >> 4;
        int kb = gl * 4;
        float2 s0 = scsh[kb], s1 = scsh[kb + 1], s2 = scsh[kb + 2], s3 = scsh[kb + 3];
        for (int g = 0; g < 16; g++) {
            int node = g * 8 + gn;
            int n = nbase + node; if (n >= n_nodes) n = n_nodes - 1;
            float4 a = gather_node(hh_in, rowptr, col, n, gl);
            tile[(kb + 0) * TS + node] = fmaxf(fmaf(a.x, s0.x, s0.y), 0.f);
            tile[(kb + 1) * TS + node] = fmaxf(fmaf(a.y, s1.x, s1.y), 0.f);
            tile[(kb + 2) * TS + node] = fmaxf(fmaf(a.z, s2.x, s2.y), 0.f);
            tile[(kb + 3) * TS + node] = fmaxf(fmaf(a.w, s3.x, s3.y), 0.f);
        }
    }
    __syncthreads();

    int half = tid & 1, q = tid >> 1;
    int halfoff = half * 32;
    int n0 = nbase + 2 * q, n1 = n0 + 1;
    bool a0 = n0 < n_nodes, a1 = n1 < n_nodes;
    int n0l = 2 * q;

    ull out[2][16];
#pragma unroll
    for (int j = 0; j < 16; j++) { out[0][j] = 0ull; out[1][j] = 0ull; }
#pragma unroll 4
    for (int k = 0; k < 64; k++) {
        float2 hv = *(const float2*)&tile[k * TS + n0l];
        fma_k32_dual(out[0], out[1], ws, k, halfoff, hv.x, hv.y);
    }

    uint2* o0 = hh_out + (size_t)n0 * 16;
    uint2* o1 = hh_out + (size_t)n1 * 16;
    float* p0 = a0 ? (pool + (size_t)__ldg(batch + n0) * 192 + pool_off) : pool;
    float* p1 = a1 ? (pool + (size_t)__ldg(batch + n1) * 192 + pool_off) : pool;
    epi_node(out[0], halfoff, b2, o0, p0, a0);
    epi_node(out[1], halfoff, b2, o1, p1, a1);
}

// ---------------------------------------------------------------------------
// fused64 (layers 2/3): gather z=pull(hh_in); GEMM1(w1); BN+ReLU; GEMM2(w2);
// fp16 store to hh_out + pool reduction. dyn smem: tile 64*TS + ws 64*64.
// ---------------------------------------------------------------------------
__global__ __launch_bounds__(128) void fused64_kernel(
    const uint2* __restrict__ hh_in,
    const int* __restrict__ rowptr, const int* __restrict__ col,
    const float* __restrict__ w1, const float* __restrict__ b1,
    const float* __restrict__ gg, const float* __restrict__ bt,
    const float* __restrict__ rm, const float* __restrict__ rv,
    const float* __restrict__ w2, const float* __restrict__ b2,
    uint2*       __restrict__ hh_out,
    const int*   __restrict__ batch,
    float*       __restrict__ pool, int pool_off, int n_nodes)
{
    extern __shared__ float dsm[];
    float* tile = dsm;                 // [64][TS]
    float* ws   = dsm + 64 * TS;       // [64][64]
    int tid = threadIdx.x;
    for (int i = tid; i < 64 * 64; i += 128) ws[i] = w1[i];
    __syncthreads();

    int nbase = blockIdx.x * 128;
    // ---- gather phase ----
    {
        int gl = tid & 15, gn = tid >> 4;
        int kb = gl * 4;
        for (int g = 0; g < 16; g++) {
            int node = g * 8 + gn;
            int n = nbase + node; if (n >= n_nodes) n = n_nodes - 1;
            float4 a = gather_node(hh_in, rowptr, col, n, gl);
            tile[(kb + 0) * TS + node] = a.x;
            tile[(kb + 1) * TS + node] = a.y;
            tile[(kb + 2) * TS + node] = a.z;
            tile[(kb + 3) * TS + node] = a.w;
        }
    }
    __syncthreads();

    int half = tid & 1, q = tid >> 1;
    int halfoff = half * 32;
    int n0 = nbase + 2 * q, n1 = n0 + 1;
    bool a0 = n0 < n_nodes, a1 = n1 < n_nodes;
    int n0l = 2 * q;

    // ---- GEMM1 ----
    ull acc[2][16];
#pragma unroll
    for (int j = 0; j < 16; j++) { acc[0][j] = 0ull; acc[1][j] = 0ull; }
#pragma unroll 4
    for (int k = 0; k < 64; k++) {
        float2 hv = *(const float2*)&tile[k * TS + n0l];
        fma_k32_dual(acc[0], acc[1], ws, k, halfoff, hv.x, hv.y);
    }
    __syncthreads();   // done reading tile + ws

    // ---- BN + ReLU -> write h back into tile; reload ws with w2 ----
#pragma unroll
    for (int j2 = 0; j2 < 16; j2++) {
        int j = halfoff + 2 * j2;
        bn_pair(acc[0][j2], acc[1][j2], j, b1, gg, bt, rm, rv);
        float x0, x1, y0, y1;
        unpack2(acc[0][j2], x0, x1);
        unpack2(acc[1][j2], y0, y1);
        *(float2*)&tile[(j + 0) * TS + n0l] = make_float2(x0, y0);
        *(float2*)&tile[(j + 1) * TS + n0l] = make_float2(x1, y1);
    }
    for (int i = tid; i < 64 * 64; i += 128) ws[i] = w2[i];
    __syncthreads();

    // ---- GEMM2 ----
    ull out[2][16];
#pragma unroll
    for (int j = 0; j < 16; j++) { out[0][j] = 0ull; out[1][j] = 0ull; }
#pragma unroll 4
    for (int k = 0; k < 64; k++) {
        float2 hv = *(const float2*)&tile[k * TS + n0l];
        fma_k32_dual(out[0], out[1], ws, k, halfoff, hv.x, hv.y);
    }

    uint2* o0 = hh_out + (size_t)n0 * 16;
    uint2* o1 = hh_out + (size_t)n1 * 16;
    float* p0 = a0 ? (pool + (size_t)__ldg(batch + n0) * 192 + pool_off) : pool;
    float* p1 = a1 ? (pool + (size_t)__ldg(batch + n1) * 192 + pool_off) : pool;
    epi_node(out[0], halfoff, b2, o0, p0, a0);
    epi_node(out[1], halfoff, b2, o1, p1, a1);
}

// ---------------------------------------------------------------------------
__global__ void final_kernel(const float* __restrict__ pool,
                             const float* __restrict__ lw1, const float* __restrict__ lb1,
                             const float* __restrict__ lw2, const float* __restrict__ lb2,
                             float* __restrict__ out)
{
    __shared__ float prow[192];
    __shared__ float hid[64];
    __shared__ float zz[2];
    int g = blockIdx.x, j = threadIdx.x;
    for (int k = j; k < 192; k += 64) prow[k] = pool[g * 192 + k];
    __syncthreads();
    float a = __ldg(lb1 + j);
    for (int k = 0; k < 192; k++) a = fmaf(prow[k], __ldg(lw1 + k * 64 + j), a);
    hid[j] = fmaxf(a, 0.f);
    __syncthreads();
    if (j < 2) {
        float z = __ldg(lb2 + j);
#pragma unroll 8
        for (int k = 0; k < 64; k++) z = fmaf(hid[k], __ldg(lw2 + k * 2 + j), z);
        zz[j] = z;
    }
    __syncthreads();
    if (j == 0) {
        float m   = fmaxf(zz[0], zz[1]);
        float lse = m + logf(expf(zz[0] - m) + expf(zz[1] - m));
        out[g * 2 + 0] = zz[0] - lse;
        out[g * 2 + 1] = zz[1] - lse;
    }
}

// ---------------------------------------------------------------------------
extern "C" void kernel_launch(void* const* d_in, const int* in_sizes, int n_in,
                              void* d_out, int out_size)
{
    const float* x     = (const float*)d_in[0];
    const int*   ei    = (const int*)  d_in[1];
    const int*   batch = (const int*)  d_in[2];

    int wi = (in_sizes[3] < 64) ? 4 : 3;
    const float* W[28];
    for (int i = 0; i < 28 && wi + i < n_in; i++) W[i] = (const float*)d_in[wi + i];

    int n_nodes = in_sizes[0] / 128;
    int n_edges = in_sizes[1] / 2;

    float *pool;
    uint2 *hhA, *hhB;
    int *deg, *row, *cur, *col, *bsum;
    cudaGetSymbolAddress((void**)&hhA,  g_hhA);
    cudaGetSymbolAddress((void**)&hhB,  g_hhB);
    cudaGetSymbolAddress((void**)&pool, g_pool);
    cudaGetSymbolAddress((void**)&deg,  g_deg);
    cudaGetSymbolAddress((void**)&row,  g_row);
    cudaGetSymbolAddress((void**)&cur,  g_cur);
    cudaGetSymbolAddress((void**)&col,  g_col);
    cudaGetSymbolAddress((void**)&bsum, g_bsum);

    float* out = (float*)d_out;

    const int SM_F = (64 * TS + 64 * 64) * 4;    // fusedB/fused64 dyn smem (~50KB)
    cudaFuncSetAttribute(fusedB_kernel,  cudaFuncAttributeMaxDynamicSharedMemorySize, SM_F);
    cudaFuncSetAttribute(fused64_kernel, cudaFuncAttributeMaxDynamicSharedMemorySize, SM_F);

    int mlpBlocks  = (n_nodes + 127) / 128;
    int scanBlocks = (n_nodes + SCAN_B - 1) / SCAN_B;

    // ---- CSR build (gemmA independent, placed mid-build) ----
    zero_i_kernel<<<(n_nodes + 1 + 255) / 256, 256>>>(deg, n_nodes + 1);
    zero_f_kernel<<<(NGRAPH * 192 + 255) / 256, 256>>>(pool, NGRAPH * 192);
    hist_kernel<<<(n_edges + 255) / 256, 256>>>(ei, deg, n_edges);
    bsum_kernel<<<scanBlocks, SCAN_B>>>(deg, bsum, n_nodes);
    bscan_kernel<<<1, 32>>>(bsum, scanBlocks);
    gemmA_kernel<<<mlpBlocks, 128>>>(x, W[0], hhA, n_nodes);
    scatter_scan_kernel<<<scanBlocks, SCAN_B>>>(deg, bsum, row, cur, n_nodes);
    fill_kernel<<<(n_edges + 255) / 256, 256>>>(ei, cur, col, n_edges);

    // ---- layer 1: hhB = mlpB(pull(hhA)) ----
    fusedB_kernel<<<mlpBlocks, 128, SM_F>>>(hhA, row, col,
        W[1], W[2], W[3], W[4], W[5], W[6], W[7],
        hhB, batch, pool, 0, n_nodes);

    // ---- layer 2: hhA = mlp(pull(hhB)) ----
    fused64_kernel<<<mlpBlocks, 128, SM_F>>>(hhB, row, col,
        W[8], W[9], W[10], W[11], W[12], W[13], W[14], W[15],
        hhA, batch, pool, 64, n_nodes);

    // ---- layer 3: hhB = mlp(pull(hhA)) ----
    fused64_kernel<<<mlpBlocks, 128, SM_F>>>(hhA, row, col,
        W[16], W[17], W[18], W[19], W[20], W[21], W[22], W[23],
        hhB, batch, pool, 128, n_nodes);

    final_kernel<<<NGRAPH, 64>>>(pool, W[24], W[25], W[26], W[27], out);
}

// round 10
// speedup vs baseline: 1.2611x; 1.2611x over previous
#include <cuda_runtime.h>
#include <cuda_fp16.h>
#include <math.h>

// ---------------------------------------------------------------------------
// GIN (3 GINConv layers + BN + ReLU + MLP head)
//   N_NODES=100000, N_EDGES=1200000, D_IN=128, D_H=64, N_GRAPHS=256
// R9: full revert to the 460.8us R6 pipeline (R7 staging and R8 fusion both
// regressed), plus risk-free trims:
//   * zero_i+zero_f merged into one kernel
//   * bscan folded into scatter_scan (inline warp-reduce of block offsets)
//   * gemmA moved to our 4th launch so the ncu window profiles it
// ---------------------------------------------------------------------------

#define MAX_NODES 100000
#define MAX_EDGES 1200000
#define NGRAPH    256
#define SCAN_B    1024
#define MAX_SCAN_BLOCKS 128

__device__ float g_z   [MAX_NODES * 64];    // fp32 aggregated rows (pull output)
__device__ uint2 g_hh  [MAX_NODES * 16];    // fp16 activation rows (128B/node)
__device__ float g_pool[NGRAPH * 192];
__device__ int   g_deg [MAX_NODES + 1];
__device__ int   g_row [MAX_NODES + 1];
__device__ int   g_cur [MAX_NODES];
__device__ int   g_col [MAX_EDGES];
__device__ int   g_bsum[MAX_SCAN_BLOCKS];

typedef unsigned long long ull;

__device__ __forceinline__ ull pack2(float lo, float hi) {
    ull r; asm("mov.b64 %0,{%1,%2};" : "=l"(r) : "f"(lo), "f"(hi)); return r;
}
__device__ __forceinline__ void unpack2(ull v, float& lo, float& hi) {
    asm("mov.b64 {%0,%1},%2;" : "=f"(lo), "=f"(hi) : "l"(v));
}
__device__ __forceinline__ ull fma2(ull a, ull b, ull c) {
    ull d; asm("fma.rn.f32x2 %0,%1,%2,%3;" : "=l"(d) : "l"(a), "l"(b), "l"(c)); return d;
}
__device__ __forceinline__ float4 h2f4(uint2 u) {
    __half2 a = *(__half2*)&u.x, b = *(__half2*)&u.y;
    float2 fa = __half22float2(a), fb = __half22float2(b);
    return make_float4(fa.x, fa.y, fb.x, fb.y);
}
__device__ __forceinline__ uint2 f4h(float a, float b, float c, float d) {
    __half2 lo = __floats2half2_rn(a, b), hi = __floats2half2_rn(c, d);
    uint2 u; u.x = *(unsigned*)&lo; u.y = *(unsigned*)&hi; return u;
}

// One k-step: one weight row segment (32 cols) feeds TWO nodes' accumulators.
__device__ __forceinline__ void fma_k32_dual(ull* accA, ull* accB,
                                             const float* ws, int k, int halfoff,
                                             float va, float vb) {
    ull a2 = pack2(va, va), b2 = pack2(vb, vb);
    const ulonglong2* wrow = (const ulonglong2*)(ws + k * 64 + halfoff);
#pragma unroll
    for (int j8 = 0; j8 < 8; j8++) {
        ulonglong2 wv = wrow[j8];
        accA[j8 * 2 + 0] = fma2(a2, wv.x, accA[j8 * 2 + 0]);
        accA[j8 * 2 + 1] = fma2(a2, wv.y, accA[j8 * 2 + 1]);
        accB[j8 * 2 + 0] = fma2(b2, wv.x, accB[j8 * 2 + 0]);
        accB[j8 * 2 + 1] = fma2(b2, wv.y, accB[j8 * 2 + 1]);
    }
}

// BN(eval)+ReLU for col pair (j, j+1) applied to both nodes' packed values.
__device__ __forceinline__ void bn_pair(ull& va, ull& vb, int j,
    const float* __restrict__ b1, const float* __restrict__ gg,
    const float* __restrict__ bt, const float* __restrict__ rm,
    const float* __restrict__ rv)
{
    float sc0 = __ldg(gg + j)     * rsqrtf(__ldg(rv + j)     + 1e-5f);
    float sc1 = __ldg(gg + j + 1) * rsqrtf(__ldg(rv + j + 1) + 1e-5f);
    float sh0 = (__ldg(b1 + j)     - __ldg(rm + j))     * sc0 + __ldg(bt + j);
    float sh1 = (__ldg(b1 + j + 1) - __ldg(rm + j + 1)) * sc1 + __ldg(bt + j + 1);
    float a, b;
    unpack2(va, a, b);
    a = fmaxf(fmaf(a, sc0, sh0), 0.f);
    b = fmaxf(fmaf(b, sc1, sh1), 0.f);
    va = pack2(a, b);
    unpack2(vb, a, b);
    a = fmaxf(fmaf(a, sc0, sh0), 0.f);
    b = fmaxf(fmaf(b, sc1, sh1), 0.f);
    vb = pack2(a, b);
}

// Epilogue for one node's 32 cols: bias + ReLU + fp16 store + pool reduction.
__device__ __forceinline__ void epi_node(const ull* out16, int halfoff,
                                         const float* __restrict__ b2,
                                         uint2* hrow, float* prow, bool act)
{
    if (!act) return;
    int ubase = halfoff >> 2;
#pragma unroll
    for (int qq = 0; qq < 8; qq++) {
        int j = halfoff + qq * 4;
        float a0, a1, a2, a3;
        unpack2(out16[qq * 2 + 0], a0, a1);
        unpack2(out16[qq * 2 + 1], a2, a3);
        a0 = fmaxf(a0 + __ldg(b2 + j + 0), 0.f);
        a1 = fmaxf(a1 + __ldg(b2 + j + 1), 0.f);
        a2 = fmaxf(a2 + __ldg(b2 + j + 2), 0.f);
        a3 = fmaxf(a3 + __ldg(b2 + j + 3), 0.f);
        hrow[ubase + qq] = f4h(a0, a1, a2, a3);
        asm volatile("red.global.add.v4.f32 [%0], {%1,%2,%3,%4};"
                     :: "l"(prow + j), "f"(a0), "f"(a1), "f"(a2), "f"(a3)
                     : "memory");
    }
}

// ---------------------------------------------------------------------------
// zero_both: deg and pool cleared in one launch
// ---------------------------------------------------------------------------
__global__ void zero_both_kernel(int* __restrict__ deg, int nd,
                                 float* __restrict__ pool, int np) {
    int i = blockIdx.x * blockDim.x + threadIdx.x;
    if (i < nd) deg[i] = 0;
    if (i < np) pool[i] = 0.f;
}

// ---------------------------------------------------------------------------
// CSR build
// ---------------------------------------------------------------------------
__global__ void hist_kernel(const int* __restrict__ ei, int* __restrict__ deg, int n_edges) {
    int e = blockIdx.x * blockDim.x + threadIdx.x;
    if (e < n_edges) atomicAdd(deg + __ldg(ei + n_edges + e), 1);
}

__global__ void bsum_kernel(const int* __restrict__ deg, int* __restrict__ bsum, int n) {
    __shared__ int sm[SCAN_B];
    int i = blockIdx.x * SCAN_B + threadIdx.x;
    sm[threadIdx.x] = (i < n) ? deg[i] : 0;
    __syncthreads();
#pragma unroll
    for (int off = SCAN_B / 2; off > 0; off >>= 1) {
        if (threadIdx.x < off) sm[threadIdx.x] += sm[threadIdx.x + off];
        __syncthreads();
    }
    if (threadIdx.x == 0) bsum[blockIdx.x] = sm[0];
}

// Hillis-Steele block scan; block offset computed INLINE (warp-reduce over
// bsum[0..bid), nb <= 98) so the separate bscan launch is gone.
__global__ void scatter_scan_kernel(const int* __restrict__ deg,
                                    const int* __restrict__ bsum,
                                    int* __restrict__ rowptr, int* __restrict__ cur, int n) {
    __shared__ int sm[SCAN_B];
    __shared__ int boff;
    int bid = blockIdx.x;
    if (threadIdx.x < 32) {
        int s = 0;
        for (int i = threadIdx.x; i < bid; i += 32) s += __ldg(bsum + i);
#pragma unroll
        for (int o = 16; o > 0; o >>= 1) s += __shfl_down_sync(0xffffffffu, s, o);
        if (threadIdx.x == 0) boff = s;
    }
    int i = bid * SCAN_B + threadIdx.x;
    int v = (i < n) ? deg[i] : 0;
    sm[threadIdx.x] = v;
    __syncthreads();     // also publishes boff
#pragma unroll
    for (int off = 1; off < SCAN_B; off *= 2) {
        int t = (threadIdx.x >= off) ? sm[threadIdx.x - off] : 0;
        __syncthreads();
        sm[threadIdx.x] += t;
        __syncthreads();
    }
    int excl = sm[threadIdx.x] - v + boff;
    if (i < n) { rowptr[i] = excl; cur[i] = excl; }
    if (i == n - 1) rowptr[n] = excl + v;
}

__global__ void fill_kernel(const int* __restrict__ ei, int* __restrict__ cur,
                            int* __restrict__ col, int n_edges) {
    int e = blockIdx.x * blockDim.x + threadIdx.x;
    if (e >= n_edges) return;
    int s = __ldg(ei + e);
    int d = __ldg(ei + n_edges + e);
    int pos = atomicAdd(cur + d, 1);
    col[pos] = s;
}

// ---------------------------------------------------------------------------
// Pull aggregation over fp16 rows (fp32 accumulate, fp32 out). 16 thr/node.
// (identical to the 460.8us R6 kernel)
// ---------------------------------------------------------------------------
__global__ void pull64h_kernel(const uint2* __restrict__ hh,
                               const int* __restrict__ rowptr,
                               const int* __restrict__ col,
                               float* __restrict__ zout, int n_nodes) {
    int t = blockIdx.x * blockDim.x + threadIdx.x;
    int node = t >> 4, lane = t & 15;
    if (node >= n_nodes) return;
    float4 acc = h2f4(__ldg(hh + (size_t)node * 16 + lane));
    int e   = __ldg(rowptr + node);
    int end = __ldg(rowptr + node + 1);
    for (; e + 8 <= end; e += 8) {
        int s0 = __ldg(col + e),     s1 = __ldg(col + e + 1);
        int s2 = __ldg(col + e + 2), s3 = __ldg(col + e + 3);
        int s4 = __ldg(col + e + 4), s5 = __ldg(col + e + 5);
        int s6 = __ldg(col + e + 6), s7 = __ldg(col + e + 7);
        float4 v0 = h2f4(__ldg(hh + (size_t)s0 * 16 + lane));
        float4 v1 = h2f4(__ldg(hh + (size_t)s1 * 16 + lane));
        float4 v2 = h2f4(__ldg(hh + (size_t)s2 * 16 + lane));
        float4 v3 = h2f4(__ldg(hh + (size_t)s3 * 16 + lane));
        float4 v4 = h2f4(__ldg(hh + (size_t)s4 * 16 + lane));
        float4 v5 = h2f4(__ldg(hh + (size_t)s5 * 16 + lane));
        float4 v6 = h2f4(__ldg(hh + (size_t)s6 * 16 + lane));
        float4 v7 = h2f4(__ldg(hh + (size_t)s7 * 16 + lane));
        acc.x += ((v0.x + v1.x) + (v2.x + v3.x)) + ((v4.x + v5.x) + (v6.x + v7.x));
        acc.y += ((v0.y + v1.y) + (v2.y + v3.y)) + ((v4.y + v5.y) + (v6.y + v7.y));
        acc.z += ((v0.z + v1.z) + (v2.z + v3.z)) + ((v4.z + v5.z) + (v6.z + v7.z));
        acc.w += ((v0.w + v1.w) + (v2.w + v3.w)) + ((v4.w + v5.w) + (v6.w + v7.w));
    }
    for (; e + 4 <= end; e += 4) {
        int s0 = __ldg(col + e),     s1 = __ldg(col + e + 1);
        int s2 = __ldg(col + e + 2), s3 = __ldg(col + e + 3);
        float4 v0 = h2f4(__ldg(hh + (size_t)s0 * 16 + lane));
        float4 v1 = h2f4(__ldg(hh + (size_t)s1 * 16 + lane));
        float4 v2 = h2f4(__ldg(hh + (size_t)s2 * 16 + lane));
        float4 v3 = h2f4(__ldg(hh + (size_t)s3 * 16 + lane));
        acc.x += (v0.x + v1.x) + (v2.x + v3.x);
        acc.y += (v0.y + v1.y) + (v2.y + v3.y);
        acc.z += (v0.z + v1.z) + (v2.z + v3.z);
        acc.w += (v0.w + v1.w) + (v2.w + v3.w);
    }
    for (; e < end; e++) {
        int s = __ldg(col + e);
        float4 v = h2f4(__ldg(hh + (size_t)s * 16 + lane));
        acc.x += v.x; acc.y += v.y; acc.z += v.z; acc.w += v.w;
    }
    ((float4*)zout)[(size_t)node * 16 + lane] = acc;
}

// ---------------------------------------------------------------------------
// gemmA: hh = fp16(x @ w1)  (x: [N,128]). 2 nodes/thread, 32 cols each.
// (identical to R6; our 4th launch -> profiled by ncu)
// ---------------------------------------------------------------------------
__global__ __launch_bounds__(128) void gemmA_kernel(
    const float* __restrict__ x, const float* __restrict__ w1,
    uint2* __restrict__ hh, int n_nodes)
{
    __shared__ float ws[128 * 64];   // 32KB
    int tid = threadIdx.x;
    for (int i = tid; i < 128 * 64; i += 128) ws[i] = w1[i];
    __syncthreads();

    int half = tid & 1, q = tid >> 1;
    int halfoff = half * 32;
    int n0 = blockIdx.x * 128 + 2 * q, n1 = n0 + 1;
    bool a0 = n0 < n_nodes, a1 = n1 < n_nodes;
    int n0c = a0 ? n0 : n_nodes - 1, n1c = a1 ? n1 : n_nodes - 1;

    ull acc[2][16];
#pragma unroll
    for (int j = 0; j < 16; j++) { acc[0][j] = 0ull; acc[1][j] = 0ull; }

    const float4* r0 = (const float4*)(x + (size_t)n0c * 128);
    const float4* r1 = (const float4*)(x + (size_t)n1c * 128);
#pragma unroll 4
    for (int k4 = 0; k4 < 32; k4++) {
        float4 v0 = __ldg(r0 + k4), v1 = __ldg(r1 + k4);
        float f0[4] = {v0.x, v0.y, v0.z, v0.w};
        float f1[4] = {v1.x, v1.y, v1.z, v1.w};
#pragma unroll
        for (int kk = 0; kk < 4; kk++)
            fma_k32_dual(acc[0], acc[1], ws, k4 * 4 + kk, halfoff, f0[kk], f1[kk]);
    }

    int ubase = halfoff >> 2;
#pragma unroll
    for (int nd = 0; nd < 2; nd++) {
        bool act = nd ? a1 : a0;
        if (!act) continue;
        int n = nd ? n1 : n0;
        uint2* orow = hh + (size_t)n * 16;
#pragma unroll
        for (int qq = 0; qq < 8; qq++) {
            float a, b, c, d;
            unpack2(acc[nd][qq * 2 + 0], a, b);
            unpack2(acc[nd][qq * 2 + 1], c, d);
            orow[ubase + qq] = f4h(a, b, c, d);
        }
    }
}

// ---------------------------------------------------------------------------
// mlpB (layer-1 tail): h = relu( relu(BN(z+b1)) @ w2 + b2 ); fp16 store + pool.
// (identical to R6: strided z load + BN into 32KB tile, GEMM2 from tile)
// ---------------------------------------------------------------------------
__global__ __launch_bounds__(128) void mlpB_kernel(
    const float* __restrict__ z,
    const float* __restrict__ b1,
    const float* __restrict__ gg, const float* __restrict__ bt,
    const float* __restrict__ rm, const float* __restrict__ rv,
    const float* __restrict__ w2, const float* __restrict__ b2,
    uint2*       __restrict__ hh,
    const int*   __restrict__ batch,
    float*       __restrict__ pool, int pool_off, int n_nodes)
{
    __shared__ float ws[64 * 64];      // 16KB (w2)
    __shared__ float tile[64 * 128];   // 32KB [col][node]
    int tid = threadIdx.x;
    for (int i = tid; i < 64 * 64; i += 128) ws[i] = w2[i];

    int half = tid & 1, q = tid >> 1;
    int halfoff = half * 32;
    int n0 = blockIdx.x * 128 + 2 * q, n1 = n0 + 1;
    bool a0 = n0 < n_nodes, a1 = n1 < n_nodes;
    int n0c = a0 ? n0 : n_nodes - 1, n1c = a1 ? n1 : n_nodes - 1;

    const float4* zr0 = (const float4*)(z + (size_t)n0c * 64 + halfoff);
    const float4* zr1 = (const float4*)(z + (size_t)n1c * 64 + halfoff);
#pragma unroll
    for (int qq = 0; qq < 8; qq++) {
        float4 v0 = __ldg(zr0 + qq), v1 = __ldg(zr1 + qq);
        ull p00 = pack2(v0.x, v0.y), p01 = pack2(v0.z, v0.w);
        ull p10 = pack2(v1.x, v1.y), p11 = pack2(v1.z, v1.w);
        int j = halfoff + qq * 4;
        bn_pair(p00, p10, j,     b1, gg, bt, rm, rv);
        bn_pair(p01, p11, j + 2, b1, gg, bt, rm, rv);
        float x0, x1, y0, y1;
        unpack2(p00, x0, x1); unpack2(p10, y0, y1);
        *(float2*)&tile[(j + 0) * 128 + 2 * q] = make_float2(x0, y0);
        *(float2*)&tile[(j + 1) * 128 + 2 * q] = make_float2(x1, y1);
        unpack2(p01, x0, x1); unpack2(p11, y0, y1);
        *(float2*)&tile[(j + 2) * 128 + 2 * q] = make_float2(x0, y0);
        *(float2*)&tile[(j + 3) * 128 + 2 * q] = make_float2(x1, y1);
    }
    __syncthreads();

    ull out[2][16];
#pragma unroll
    for (int j = 0; j < 16; j++) { out[0][j] = 0ull; out[1][j] = 0ull; }
#pragma unroll 4
    for (int k = 0; k < 64; k++) {
        float2 hv = *(const float2*)&tile[k * 128 + 2 * q];
        fma_k32_dual(out[0], out[1], ws, k, halfoff, hv.x, hv.y);
    }

    uint2* o0 = hh + (size_t)n0 * 16;
    uint2* o1 = hh + (size_t)n1 * 16;
    float* p0 = a0 ? (pool + (size_t)__ldg(batch + n0) * 192 + pool_off) : pool;
    float* p1 = a1 ? (pool + (size_t)__ldg(batch + n1) * 192 + pool_off) : pool;
    epi_node(out[0], halfoff, b2, o0, p0, a0);
    epi_node(out[1], halfoff, b2, o1, p1, a1);
}

// ---------------------------------------------------------------------------
// mlp64: full fused layer (layers 2/3). (identical to R6)
// ---------------------------------------------------------------------------
__global__ __launch_bounds__(128) void mlp64_kernel(
    const float* __restrict__ agg,
    const float* __restrict__ w1, const float* __restrict__ b1,
    const float* __restrict__ gg, const float* __restrict__ bt,
    const float* __restrict__ rm, const float* __restrict__ rv,
    const float* __restrict__ w2, const float* __restrict__ b2,
    uint2*       __restrict__ hh,
    const int*   __restrict__ batch,
    float*       __restrict__ pool, int pool_off, int n_nodes)
{
    __shared__ float ws[64 * 64];      // 16KB (w1 then w2)
    __shared__ float tile[64 * 128];   // 32KB [col][node]
    int tid = threadIdx.x;
    for (int i = tid; i < 64 * 64; i += 128) ws[i] = w1[i];
    __syncthreads();

    int half = tid & 1, q = tid >> 1;
    int halfoff = half * 32;
    int n0 = blockIdx.x * 128 + 2 * q, n1 = n0 + 1;
    bool a0 = n0 < n_nodes, a1 = n1 < n_nodes;
    int n0c = a0 ? n0 : n_nodes - 1, n1c = a1 ? n1 : n_nodes - 1;

    // ---- GEMM1 (strided row loads into regs) ----
    ull acc[2][16];
#pragma unroll
    for (int j = 0; j < 16; j++) { acc[0][j] = 0ull; acc[1][j] = 0ull; }

    const float4* r0 = (const float4*)(agg + (size_t)n0c * 64);
    const float4* r1 = (const float4*)(agg + (size_t)n1c * 64);
#pragma unroll 4
    for (int k4 = 0; k4 < 16; k4++) {
        float4 v0 = __ldg(r0 + k4), v1 = __ldg(r1 + k4);
        float f0[4] = {v0.x, v0.y, v0.z, v0.w};
        float f1[4] = {v1.x, v1.y, v1.z, v1.w};
#pragma unroll
        for (int kk = 0; kk < 4; kk++)
            fma_k32_dual(acc[0], acc[1], ws, k4 * 4 + kk, halfoff, f0[kk], f1[kk]);
    }

    // ---- BN + ReLU -> write h into tile ----
#pragma unroll
    for (int j2 = 0; j2 < 16; j2++) {
        int j = halfoff + 2 * j2;
        bn_pair(acc[0][j2], acc[1][j2], j, b1, gg, bt, rm, rv);
        float x0, x1, y0, y1;
        unpack2(acc[0][j2], x0, x1);
        unpack2(acc[1][j2], y0, y1);
        *(float2*)&tile[(j + 0) * 128 + 2 * q] = make_float2(x0, y0);
        *(float2*)&tile[(j + 1) * 128 + 2 * q] = make_float2(x1, y1);
    }

    // ---- swap weights ----
    __syncthreads();
    for (int i = tid; i < 64 * 64; i += 128) ws[i] = w2[i];
    __syncthreads();

    // ---- GEMM2 ----
    ull out[2][16];
#pragma unroll
    for (int j = 0; j < 16; j++) { out[0][j] = 0ull; out[1][j] = 0ull; }
#pragma unroll 4
    for (int k = 0; k < 64; k++) {
        float2 hv = *(const float2*)&tile[k * 128 + 2 * q];
        fma_k32_dual(out[0], out[1], ws, k, halfoff, hv.x, hv.y);
    }

    uint2* o0 = hh + (size_t)n0 * 16;
    uint2* o1 = hh + (size_t)n1 * 16;
    float* p0 = a0 ? (pool + (size_t)__ldg(batch + n0) * 192 + pool_off) : pool;
    float* p1 = a1 ? (pool + (size_t)__ldg(batch + n1) * 192 + pool_off) : pool;
    epi_node(out[0], halfoff, b2, o0, p0, a0);
    epi_node(out[1], halfoff, b2, o1, p1, a1);
}

// ---------------------------------------------------------------------------
__global__ void final_kernel(const float* __restrict__ pool,
                             const float* __restrict__ lw1, const float* __restrict__ lb1,
                             const float* __restrict__ lw2, const float* __restrict__ lb2,
                             float* __restrict__ out)
{
    __shared__ float prow[192];
    __shared__ float hid[64];
    __shared__ float zz[2];
    int g = blockIdx.x, j = threadIdx.x;
    for (int k = j; k < 192; k += 64) prow[k] = pool[g * 192 + k];
    __syncthreads();
    float a = __ldg(lb1 + j);
    for (int k = 0; k < 192; k++) a = fmaf(prow[k], __ldg(lw1 + k * 64 + j), a);
    hid[j] = fmaxf(a, 0.f);
    __syncthreads();
    if (j < 2) {
        float z = __ldg(lb2 + j);
#pragma unroll 8
        for (int k = 0; k < 64; k++) z = fmaf(hid[k], __ldg(lw2 + k * 2 + j), z);
        zz[j] = z;
    }
    __syncthreads();
    if (j == 0) {
        float m   = fmaxf(zz[0], zz[1]);
        float lse = m + logf(expf(zz[0] - m) + expf(zz[1] - m));
        out[g * 2 + 0] = zz[0] - lse;
        out[g * 2 + 1] = zz[1] - lse;
    }
}

// ---------------------------------------------------------------------------
extern "C" void kernel_launch(void* const* d_in, const int* in_sizes, int n_in,
                              void* d_out, int out_size)
{
    const float* x     = (const float*)d_in[0];
    const int*   ei    = (const int*)  d_in[1];
    const int*   batch = (const int*)  d_in[2];

    int wi = (in_sizes[3] < 64) ? 4 : 3;
    const float* W[28];
    for (int i = 0; i < 28 && wi + i < n_in; i++) W[i] = (const float*)d_in[wi + i];

    int n_nodes = in_sizes[0] / 128;
    int n_edges = in_sizes[1] / 2;

    float *z, *pool;
    uint2 *hh;
    int *deg, *row, *cur, *col, *bsum;
    cudaGetSymbolAddress((void**)&z,    g_z);
    cudaGetSymbolAddress((void**)&hh,   g_hh);
    cudaGetSymbolAddress((void**)&pool, g_pool);
    cudaGetSymbolAddress((void**)&deg,  g_deg);
    cudaGetSymbolAddress((void**)&row,  g_row);
    cudaGetSymbolAddress((void**)&cur,  g_cur);
    cudaGetSymbolAddress((void**)&col,  g_col);
    cudaGetSymbolAddress((void**)&bsum, g_bsum);

    float* out = (float*)d_out;

    int mlpBlocks  = (n_nodes + 127) / 128;
    int pullBlocks = (n_nodes * 16 + 255) / 256;
    int scanBlocks = (n_nodes + SCAN_B - 1) / SCAN_B;
    int zeroN      = n_nodes + 1;   // >= NGRAPH*192

    // ---- CSR build; gemmA is OUR launch #4 (profiled by the ncu window) ----
    zero_both_kernel<<<(zeroN + 255) / 256, 256>>>(deg, zeroN, pool, NGRAPH * 192); // 1
    hist_kernel<<<(n_edges + 255) / 256, 256>>>(ei, deg, n_edges);                  // 2
    bsum_kernel<<<scanBlocks, SCAN_B>>>(deg, bsum, n_nodes);                        // 3
    gemmA_kernel<<<mlpBlocks, 128>>>(x, W[0], hh, n_nodes);                         // 4
    scatter_scan_kernel<<<scanBlocks, SCAN_B>>>(deg, bsum, row, cur, n_nodes);      // 5
    fill_kernel<<<(n_edges + 255) / 256, 256>>>(ei, cur, col, n_edges);             // 6

    // ---- layer 1 ----
    pull64h_kernel<<<pullBlocks, 256>>>(hh, row, col, z, n_nodes);                  // 7
    mlpB_kernel<<<mlpBlocks, 128>>>(z, W[1], W[2], W[3], W[4], W[5], W[6], W[7],
                                    hh, batch, pool, 0, n_nodes);                   // 8

    // ---- layer 2 ----
    pull64h_kernel<<<pullBlocks, 256>>>(hh, row, col, z, n_nodes);                  // 9
    mlp64_kernel<<<mlpBlocks, 128>>>(z, W[8], W[9], W[10], W[11], W[12], W[13], W[14], W[15],
                                     hh, batch, pool, 64, n_nodes);                 // 10

    // ---- layer 3 ----
    pull64h_kernel<<<pullBlocks, 256>>>(hh, row, col, z, n_nodes);                  // 11
    mlp64_kernel<<<mlpBlocks, 128>>>(z, W[16], W[17], W[18], W[19], W[20], W[21], W[22], W[23],
                                     hh, batch, pool, 128, n_nodes);                // 12

    final_kernel<<<NGRAPH, 64>>>(pool, W[24], W[25], W[26], W[27], out);            // 13
}